// round 4
// baseline (speedup 1.0000x reference)
#include <cuda_runtime.h>
#include <cstdint>
#include <cstddef>

#define T_LEN 2048
#define I_DIM 1739
#define H_DIM 256
#define G3    768          // 3*H
#define NCTA  8            // cluster size for the recurrence

// ---------------- scratch (module-static device globals; no runtime alloc) ----
__device__ float g_xproj_enc[T_LEN * G3];
__device__ float g_xproj_dec[T_LEN * G3];
__device__ float g_hs[T_LEN * H_DIM];
__device__ float g_henc[H_DIM];

// ---------------- fp32 tiled GEMM:  C[M,N] = A[M,K] @ B[N,K]^T + bias[N] -----
#define BM 64
#define BN 64
#define BK 16

__global__ void __launch_bounds__(256) gemm_bias_kernel(
    const float* __restrict__ A, const float* __restrict__ B,
    const float* __restrict__ bias, float* __restrict__ C,
    int M, int N, int K)
{
    __shared__ float As[BK][BM + 4];
    __shared__ float Bs[BK][BN + 4];
    const int tid = threadIdx.x;
    const int tx = tid & 15, ty = tid >> 4;
    const int row0 = blockIdx.y * BM, col0 = blockIdx.x * BN;
    const int lc = tid & (BK - 1);     // 0..15 k-col within tile
    const int lr = tid / BK;           // 0..15 row group

    float acc[4][4] = {};

    for (int k0 = 0; k0 < K; k0 += BK) {
        #pragma unroll
        for (int i = 0; i < 4; i++) {
            const int r  = lr + i * 16;
            const int gc = k0 + lc;
            const int ga = row0 + r;          // M is always a multiple of BM here
            As[lc][r] = (gc < K) ? A[(size_t)ga * K + gc] : 0.f;
            const int gb = col0 + r;
            Bs[lc][r] = (gb < N && gc < K) ? B[(size_t)gb * K + gc] : 0.f;
        }
        __syncthreads();
        #pragma unroll
        for (int k = 0; k < BK; k++) {
            float a[4], b[4];
            #pragma unroll
            for (int i = 0; i < 4; i++) a[i] = As[k][ty * 4 + i];
            #pragma unroll
            for (int j = 0; j < 4; j++) b[j] = Bs[k][tx * 4 + j];
            #pragma unroll
            for (int i = 0; i < 4; i++)
                #pragma unroll
                for (int j = 0; j < 4; j++)
                    acc[i][j] += a[i] * b[j];
        }
        __syncthreads();
    }

    #pragma unroll
    for (int i = 0; i < 4; i++) {
        const int r = row0 + ty * 4 + i;
        #pragma unroll
        for (int j = 0; j < 4; j++) {
            const int c = col0 + tx * 4 + j;
            if (c < N) C[(size_t)r * N + c] = acc[i][j] + bias[c];
        }
    }
}

// ---------------- GRU recurrence: persistent 8-CTA cluster kernel ------------
//
// 8 CTAs x 1024 threads. Warp w of CTA c owns hidden unit j = c*32 + w, i.e.
// W_hh rows {j, j+256, j+512} (r/z/n gates). Each lane holds 8 columns of each
// of those 3 rows in registers (24 fp32 regs/thread; weights never re-fetched).
// Per step: read h (local smem, double-buffered), 24 FMAs, 3 butterfly reduces,
// lane0 computes the full gate combine for unit j and broadcasts the single
// float h_new[j] to all 8 CTAs via st.shared::cluster. One barrier.cluster/step.

__device__ __forceinline__ uint32_t smem_u32(const void* p) {
    uint32_t a;
    asm("{ .reg .u64 t; cvta.to.shared.u64 t, %1; cvt.u32.u64 %0, t; }"
        : "=r"(a) : "l"(p));
    return a;
}

__device__ __forceinline__ float sigmoid_fast(float x) {
    return __fdividef(1.f, 1.f + __expf(-x));
}
__device__ __forceinline__ float tanh_fast(float x) {
    // tanh(x) = 1 - 2/(e^{2x}+1); saturates correctly at +/-inf of expf.
    return 1.f - __fdividef(2.f, __expf(2.f * x) + 1.f);
}

__global__ void __cluster_dims__(NCTA, 1, 1) __launch_bounds__(1024, 1)
gru_kernel(const float* __restrict__ xproj, const float* __restrict__ Whh,
           const float* __restrict__ bhh,   const float* __restrict__ h0,
           float* __restrict__ hs_out,      float* __restrict__ hT_out)
{
    __shared__ __align__(16) float h_buf[2][H_DIM];

    const int tid  = threadIdx.x;
    const int wid  = tid >> 5;
    const int lane = tid & 31;
    uint32_t rank;
    asm("mov.u32 %0, %%cluster_ctarank;" : "=r"(rank));
    const int j = (int)rank * 32 + wid;          // hidden unit owned by this warp

    // Register-resident weights: rows j (r-gate), j+256 (z), j+512 (n), cols [8*lane, 8*lane+8)
    float w0[8], w1[8], w2[8];
    {
        const float4* p0 = (const float4*)(Whh + (size_t)j * H_DIM + lane * 8);
        const float4* p1 = (const float4*)(Whh + (size_t)(j + 256) * H_DIM + lane * 8);
        const float4* p2 = (const float4*)(Whh + (size_t)(j + 512) * H_DIM + lane * 8);
        float4 a = p0[0], b = p0[1];
        w0[0]=a.x; w0[1]=a.y; w0[2]=a.z; w0[3]=a.w; w0[4]=b.x; w0[5]=b.y; w0[6]=b.z; w0[7]=b.w;
        a = p1[0]; b = p1[1];
        w1[0]=a.x; w1[1]=a.y; w1[2]=a.z; w1[3]=a.w; w1[4]=b.x; w1[5]=b.y; w1[6]=b.z; w1[7]=b.w;
        a = p2[0]; b = p2[1];
        w2[0]=a.x; w2[1]=a.y; w2[2]=a.z; w2[3]=a.w; w2[4]=b.x; w2[5]=b.y; w2[6]=b.z; w2[7]=b.w;
    }
    const float bhr = bhh[j], bhz = bhh[j + 256], bhn = bhh[j + 512];

    // init h (each CTA its own copy), then cluster-sync before any remote write
    if (tid < H_DIM) {
        h_buf[0][tid] = h0 ? h0[tid] : 0.f;
        h_buf[1][tid] = 0.f;
    }
    __syncthreads();
    asm volatile("barrier.cluster.arrive.aligned;" ::: "memory");
    asm volatile("barrier.cluster.wait.aligned;"   ::: "memory");

    const uint32_t hbase = smem_u32(&h_buf[0][0]);

    for (int t = 0; t < T_LEN; t++) {
        const int p = t & 1;

        // prefetch x_proj values + h_old early (consumed ~200 cyc later)
        float xr = 0.f, xz = 0.f, xn = 0.f, hold = 0.f;
        if (lane == 0) {
            const float* row = xproj + (size_t)t * G3;
            xr = row[j]; xz = row[j + 256]; xn = row[j + 512];
            hold = h_buf[p][j];
        }

        // matvec partials: 24 FMAs over this lane's 8 h values
        const float4* hb = (const float4*)&h_buf[p][lane * 8];
        const float4 hv0 = hb[0], hv1 = hb[1];
        const float hv[8] = {hv0.x, hv0.y, hv0.z, hv0.w, hv1.x, hv1.y, hv1.z, hv1.w};
        float a0 = 0.f, a1 = 0.f, a2 = 0.f;
        #pragma unroll
        for (int k = 0; k < 8; k++) {
            a0 += w0[k] * hv[k];
            a1 += w1[k] * hv[k];
            a2 += w2[k] * hv[k];
        }
        #pragma unroll
        for (int off = 16; off > 0; off >>= 1) {
            a0 += __shfl_xor_sync(0xffffffffu, a0, off);
            a1 += __shfl_xor_sync(0xffffffffu, a1, off);
            a2 += __shfl_xor_sync(0xffffffffu, a2, off);
        }

        if (lane == 0) {
            const float r = sigmoid_fast(xr + a0 + bhr);
            const float z = sigmoid_fast(xz + a1 + bhz);
            const float n = tanh_fast(xn + r * (a2 + bhn));
            const float hnew = n + z * (hold - n);     // (1-z)*n + z*h

            // broadcast h_new[j] into every CTA's next-parity buffer
            const uint32_t off4 = hbase + (uint32_t)(((1 - p) * H_DIM + j) * 4);
            #pragma unroll
            for (int d = 0; d < NCTA; d++) {
                uint32_t ra;
                asm("mapa.shared::cluster.u32 %0, %1, %2;" : "=r"(ra) : "r"(off4), "r"(d));
                asm volatile("st.shared::cluster.f32 [%0], %1;" :: "r"(ra), "f"(hnew));
            }
            if (hs_out) hs_out[(size_t)t * H_DIM + j] = hnew;
        }

        // release all remote stores / acquire peers' stores
        asm volatile("barrier.cluster.arrive.aligned;" ::: "memory");
        asm volatile("barrier.cluster.wait.aligned;"   ::: "memory");
    }

    // T_LEN is even -> final h lives in buffer 0
    if (hT_out && rank == 0 && tid < H_DIM) hT_out[tid] = h_buf[0][tid];
}

// ---------------- launch --------------------------------------------------------
extern "C" void kernel_launch(void* const* d_in, const int* in_sizes, int n_in,
                              void* d_out, int out_size)
{
    const float* x      = (const float*)d_in[0];   // [1, T, I]
    const float* W_ih_e = (const float*)d_in[2];   // [768, 1739]
    const float* W_hh_e = (const float*)d_in[3];   // [768, 256]
    const float* b_ih_e = (const float*)d_in[4];   // [768]
    const float* b_hh_e = (const float*)d_in[5];   // [768]
    const float* W_ih_d = (const float*)d_in[6];
    const float* W_hh_d = (const float*)d_in[7];
    const float* b_ih_d = (const float*)d_in[8];
    const float* b_hh_d = (const float*)d_in[9];
    const float* W_out  = (const float*)d_in[10];  // [1739, 256]
    const float* b_out  = (const float*)d_in[11];  // [1739]
    float* out = (float*)d_out;                    // [2048, 1, 1739]

    float *xpe, *xpd, *hs, *henc;
    cudaGetSymbolAddress((void**)&xpe,  g_xproj_enc);
    cudaGetSymbolAddress((void**)&xpd,  g_xproj_dec);
    cudaGetSymbolAddress((void**)&hs,   g_hs);
    cudaGetSymbolAddress((void**)&henc, g_henc);

    const dim3 blk(256);
    // x-projections (independent)
    gemm_bias_kernel<<<dim3(G3 / BN, T_LEN / BM), blk>>>(x, W_ih_e, b_ih_e, xpe,
                                                         T_LEN, G3, I_DIM);
    gemm_bias_kernel<<<dim3(G3 / BN, T_LEN / BM), blk>>>(x, W_ih_d, b_ih_d, xpd,
                                                         T_LEN, G3, I_DIM);
    // encoder recurrence -> h_enc
    gru_kernel<<<NCTA, 1024>>>(xpe, W_hh_e, b_hh_e, nullptr, nullptr, henc);
    // decoder recurrence (h0 = h_enc) -> hs
    gru_kernel<<<NCTA, 1024>>>(xpd, W_hh_d, b_hh_d, henc, hs, nullptr);
    // output projection
    gemm_bias_kernel<<<dim3((I_DIM + BN - 1) / BN, T_LEN / BM), blk>>>(
        hs, W_out, b_out, out, T_LEN, I_DIM, H_DIM);
}

// round 5
// speedup vs baseline: 1.6681x; 1.6681x over previous
#include <cuda_runtime.h>
#include <cstdint>
#include <cstddef>

#define T_LEN 2048
#define I_DIM 1739
#define H_DIM 256
#define G3    768          // 3*H
#define NCTA  8            // cluster size for the recurrence

// ---------------- scratch (module-static device globals; no runtime alloc) ----
__device__ float g_xproj_enc[T_LEN * G3];
__device__ float g_xproj_dec[T_LEN * G3];
__device__ float g_hs[T_LEN * H_DIM];
__device__ float g_henc[H_DIM];

// ---------------- fp32 tiled GEMM:  C[M,N] = A[M,K] @ B[N,K]^T + bias[N] -----
// 128x128 tile, 256 threads, 8x8 per thread. Warp tile 32x64.
// Per-thread fragments: rows {lr*4, lr*4+16}, cols {lcn*4, lcn*4+32} so that
// LDS.128 of the B fragment is bank-conflict-free (8 lanes/phase cover 128B)
// and the A fragment is a broadcast.
#define BM 128
#define BN 128
#define BK 16

__global__ void __launch_bounds__(256) gemm_bias_kernel(
    const float* __restrict__ A, const float* __restrict__ B,
    const float* __restrict__ bias, float* __restrict__ C,
    int M, int N, int K)
{
    __shared__ float As[BK][BM + 4];
    __shared__ float Bs[BK][BN + 4];

    const int tid  = threadIdx.x;
    const int lane = tid & 31;
    const int w    = tid >> 5;            // 0..7
    const int wr   = w >> 1;              // 0..3 : warp row (32 rows each)
    const int wc   = w & 1;               // 0..1 : warp col (64 cols each)
    const int lr   = lane >> 3;           // 0..3
    const int lcn  = lane & 7;            // 0..7

    const int row0 = blockIdx.y * BM;
    const int col0 = blockIdx.x * BN;
    const int r0   = wr * 32 + lr * 4;    // within-tile row frag base
    const int c0   = wc * 64 + lcn * 4;   // within-tile col frag base

    // tile loaders: 128 rows x 16 k per tile; thread loads 8 contiguous k of 1 row
    const int lrow = tid >> 1;            // 0..127
    const int lk0  = (tid & 1) * 8;       // 0 or 8

    const float* Arow = A + (size_t)(row0 + lrow) * K;   // M multiple of 128
    const int    brow = col0 + lrow;
    const float* Brow = B + (size_t)brow * K;
    const bool   bvalid = brow < N;

    float acc[8][8] = {};

    for (int k0 = 0; k0 < K; k0 += BK) {
        #pragma unroll
        for (int i = 0; i < 8; i++) {
            const int gc = k0 + lk0 + i;
            As[lk0 + i][lrow] = (gc < K) ? Arow[gc] : 0.f;
            Bs[lk0 + i][lrow] = (bvalid && gc < K) ? Brow[gc] : 0.f;
        }
        __syncthreads();

        #pragma unroll
        for (int k = 0; k < BK; k++) {
            const float4 a0 = *(const float4*)&As[k][r0];
            const float4 a1 = *(const float4*)&As[k][r0 + 16];
            const float4 b0 = *(const float4*)&Bs[k][c0];
            const float4 b1 = *(const float4*)&Bs[k][c0 + 32];
            const float av[8] = {a0.x, a0.y, a0.z, a0.w, a1.x, a1.y, a1.z, a1.w};
            const float bv[8] = {b0.x, b0.y, b0.z, b0.w, b1.x, b1.y, b1.z, b1.w};
            #pragma unroll
            for (int i = 0; i < 8; i++)
                #pragma unroll
                for (int j = 0; j < 8; j++)
                    acc[i][j] += av[i] * bv[j];
        }
        __syncthreads();
    }

    #pragma unroll
    for (int i = 0; i < 8; i++) {
        const int r = row0 + r0 + ((i < 4) ? i : (16 + i - 4));
        #pragma unroll
        for (int j = 0; j < 8; j++) {
            const int c = col0 + c0 + ((j < 4) ? j : (32 + j - 4));
            if (c < N) C[(size_t)r * N + c] = acc[i][j] + bias[c];
        }
    }
}

// ---------------- GRU recurrence: persistent 8-CTA cluster kernel ------------
//
// 8 CTAs x 1024 threads. Warp w of CTA c owns hidden unit j = c*32 + w, i.e.
// W_hh rows {j, j+256, j+512} (r/z/n gates). Each lane holds 8 columns of each
// of those 3 rows in registers (24 fp32 regs/thread; weights never re-fetched).
// Per step: read h (local smem, double-buffered), 24 FMAs, 3 butterfly reduces,
// lane0 computes the full gate combine for unit j and broadcasts the single
// float h_new[j] to all 8 CTAs via st.shared::cluster. One barrier.cluster/step.

__device__ __forceinline__ uint32_t smem_u32(const void* p) {
    uint32_t a;
    asm("{ .reg .u64 t; cvta.to.shared.u64 t, %1; cvt.u32.u64 %0, t; }"
        : "=r"(a) : "l"(p));
    return a;
}

__device__ __forceinline__ float sigmoid_fast(float x) {
    return __fdividef(1.f, 1.f + __expf(-x));
}
__device__ __forceinline__ float tanh_fast(float x) {
    // tanh(x) = 1 - 2/(e^{2x}+1); saturates correctly at +/-inf of expf.
    return 1.f - __fdividef(2.f, __expf(2.f * x) + 1.f);
}

__global__ void __cluster_dims__(NCTA, 1, 1) __launch_bounds__(1024, 1)
gru_kernel(const float* __restrict__ xproj, const float* __restrict__ Whh,
           const float* __restrict__ bhh,   const float* __restrict__ h0,
           float* __restrict__ hs_out,      float* __restrict__ hT_out)
{
    __shared__ __align__(16) float h_buf[2][H_DIM];

    const int tid  = threadIdx.x;
    const int wid  = tid >> 5;
    const int lane = tid & 31;
    uint32_t rank;
    asm("mov.u32 %0, %%cluster_ctarank;" : "=r"(rank));
    const int j = (int)rank * 32 + wid;          // hidden unit owned by this warp

    // Register-resident weights: rows j (r-gate), j+256 (z), j+512 (n), cols [8*lane, 8*lane+8)
    float w0[8], w1[8], w2[8];
    {
        const float4* p0 = (const float4*)(Whh + (size_t)j * H_DIM + lane * 8);
        const float4* p1 = (const float4*)(Whh + (size_t)(j + 256) * H_DIM + lane * 8);
        const float4* p2 = (const float4*)(Whh + (size_t)(j + 512) * H_DIM + lane * 8);
        float4 a = p0[0], b = p0[1];
        w0[0]=a.x; w0[1]=a.y; w0[2]=a.z; w0[3]=a.w; w0[4]=b.x; w0[5]=b.y; w0[6]=b.z; w0[7]=b.w;
        a = p1[0]; b = p1[1];
        w1[0]=a.x; w1[1]=a.y; w1[2]=a.z; w1[3]=a.w; w1[4]=b.x; w1[5]=b.y; w1[6]=b.z; w1[7]=b.w;
        a = p2[0]; b = p2[1];
        w2[0]=a.x; w2[1]=a.y; w2[2]=a.z; w2[3]=a.w; w2[4]=b.x; w2[5]=b.y; w2[6]=b.z; w2[7]=b.w;
    }
    const float bhr = bhh[j], bhz = bhh[j + 256], bhn = bhh[j + 512];

    // init h (each CTA its own copy), then cluster-sync before any remote write
    if (tid < H_DIM) {
        h_buf[0][tid] = h0 ? h0[tid] : 0.f;
        h_buf[1][tid] = 0.f;
    }
    __syncthreads();
    asm volatile("barrier.cluster.arrive.aligned;" ::: "memory");
    asm volatile("barrier.cluster.wait.aligned;"   ::: "memory");

    const uint32_t hbase = smem_u32(&h_buf[0][0]);

    for (int t = 0; t < T_LEN; t++) {
        const int p = t & 1;

        // prefetch x_proj values + h_old early (consumed ~200 cyc later)
        float xr = 0.f, xz = 0.f, xn = 0.f, hold = 0.f;
        if (lane == 0) {
            const float* row = xproj + (size_t)t * G3;
            xr = row[j]; xz = row[j + 256]; xn = row[j + 512];
            hold = h_buf[p][j];
        }

        // matvec partials: 24 FMAs over this lane's 8 h values
        const float4* hb = (const float4*)&h_buf[p][lane * 8];
        const float4 hv0 = hb[0], hv1 = hb[1];
        const float hv[8] = {hv0.x, hv0.y, hv0.z, hv0.w, hv1.x, hv1.y, hv1.z, hv1.w};
        float a0 = 0.f, a1 = 0.f, a2 = 0.f;
        #pragma unroll
        for (int k = 0; k < 8; k++) {
            a0 += w0[k] * hv[k];
            a1 += w1[k] * hv[k];
            a2 += w2[k] * hv[k];
        }
        #pragma unroll
        for (int off = 16; off > 0; off >>= 1) {
            a0 += __shfl_xor_sync(0xffffffffu, a0, off);
            a1 += __shfl_xor_sync(0xffffffffu, a1, off);
            a2 += __shfl_xor_sync(0xffffffffu, a2, off);
        }

        if (lane == 0) {
            const float r = sigmoid_fast(xr + a0 + bhr);
            const float z = sigmoid_fast(xz + a1 + bhz);
            const float n = tanh_fast(xn + r * (a2 + bhn));
            const float hnew = n + z * (hold - n);     // (1-z)*n + z*h

            // broadcast h_new[j] into every CTA's next-parity buffer
            const uint32_t off4 = hbase + (uint32_t)(((1 - p) * H_DIM + j) * 4);
            #pragma unroll
            for (int d = 0; d < NCTA; d++) {
                uint32_t ra;
                asm("mapa.shared::cluster.u32 %0, %1, %2;" : "=r"(ra) : "r"(off4), "r"(d));
                asm volatile("st.shared::cluster.f32 [%0], %1;" :: "r"(ra), "f"(hnew));
            }
            if (hs_out) hs_out[(size_t)t * H_DIM + j] = hnew;
        }

        // release all remote stores / acquire peers' stores
        asm volatile("barrier.cluster.arrive.aligned;" ::: "memory");
        asm volatile("barrier.cluster.wait.aligned;"   ::: "memory");
    }

    // T_LEN is even -> final h lives in buffer 0
    if (hT_out && rank == 0 && tid < H_DIM) hT_out[tid] = h_buf[0][tid];
}

// ---------------- launch --------------------------------------------------------
extern "C" void kernel_launch(void* const* d_in, const int* in_sizes, int n_in,
                              void* d_out, int out_size)
{
    const float* x      = (const float*)d_in[0];   // [1, T, I]
    const float* W_ih_e = (const float*)d_in[2];   // [768, 1739]
    const float* W_hh_e = (const float*)d_in[3];   // [768, 256]
    const float* b_ih_e = (const float*)d_in[4];   // [768]
    const float* b_hh_e = (const float*)d_in[5];   // [768]
    const float* W_ih_d = (const float*)d_in[6];
    const float* W_hh_d = (const float*)d_in[7];
    const float* b_ih_d = (const float*)d_in[8];
    const float* b_hh_d = (const float*)d_in[9];
    const float* W_out  = (const float*)d_in[10];  // [1739, 256]
    const float* b_out  = (const float*)d_in[11];  // [1739]
    float* out = (float*)d_out;                    // [2048, 1, 1739]

    float *xpe, *xpd, *hs, *henc;
    cudaGetSymbolAddress((void**)&xpe,  g_xproj_enc);
    cudaGetSymbolAddress((void**)&xpd,  g_xproj_dec);
    cudaGetSymbolAddress((void**)&hs,   g_hs);
    cudaGetSymbolAddress((void**)&henc, g_henc);

    const dim3 blk(256);
    // x-projections (independent)
    gemm_bias_kernel<<<dim3(G3 / BN, T_LEN / BM), blk>>>(x, W_ih_e, b_ih_e, xpe,
                                                         T_LEN, G3, I_DIM);
    gemm_bias_kernel<<<dim3(G3 / BN, T_LEN / BM), blk>>>(x, W_ih_d, b_ih_d, xpd,
                                                         T_LEN, G3, I_DIM);
    // encoder recurrence -> h_enc
    gru_kernel<<<NCTA, 1024>>>(xpe, W_hh_e, b_hh_e, nullptr, nullptr, henc);
    // decoder recurrence (h0 = h_enc) -> hs
    gru_kernel<<<NCTA, 1024>>>(xpd, W_hh_d, b_hh_d, henc, hs, nullptr);
    // output projection
    gemm_bias_kernel<<<dim3((I_DIM + BN - 1) / BN, T_LEN / BM), blk>>>(
        hs, W_out, b_out, out, T_LEN, I_DIM, H_DIM);
}

// round 8
// speedup vs baseline: 2.2521x; 1.3501x over previous
#include <cuda_runtime.h>
#include <cstdint>
#include <cstddef>

#define T_LEN 2048
#define I_DIM 1739
#define H_DIM 256
#define G3    768          // 3*H
#define NCTA  8            // cluster size for the recurrence

// ---------------- scratch (module-static device globals; no runtime alloc) ----
__device__ float g_xproj_enc[T_LEN * G3];
__device__ float g_xproj_dec[T_LEN * G3];
__device__ float g_hs[T_LEN * H_DIM];
__device__ float g_henc[H_DIM];

// ---------------- fp32 tiled GEMM:  C[M,N] = A[M,K] @ B[N,K]^T + bias[N] -----
// 128x128 tile, 256 threads, 8x8 per thread. Warp tile 32x64.
#define BM 128
#define BN 128
#define BK 16

__global__ void __launch_bounds__(256) gemm_bias_kernel(
    const float* __restrict__ A, const float* __restrict__ B,
    const float* __restrict__ bias, float* __restrict__ C,
    int M, int N, int K)
{
    __shared__ float As[BK][BM + 4];
    __shared__ float Bs[BK][BN + 4];

    const int tid  = threadIdx.x;
    const int lane = tid & 31;
    const int w    = tid >> 5;            // 0..7
    const int wr   = w >> 1;              // 0..3 : warp row (32 rows each)
    const int wc   = w & 1;               // 0..1 : warp col (64 cols each)
    const int lr   = lane >> 3;           // 0..3
    const int lcn  = lane & 7;            // 0..7

    const int row0 = blockIdx.y * BM;
    const int col0 = blockIdx.x * BN;
    const int r0   = wr * 32 + lr * 4;    // within-tile row frag base
    const int c0   = wc * 64 + lcn * 4;   // within-tile col frag base

    // tile loaders: 128 rows x 16 k per tile; thread loads 8 contiguous k of 1 row
    const int lrow = tid >> 1;            // 0..127
    const int lk0  = (tid & 1) * 8;       // 0 or 8

    const float* Arow = A + (size_t)(row0 + lrow) * K;   // M multiple of 128
    const int    brow = col0 + lrow;
    const float* Brow = B + (size_t)brow * K;
    const bool   bvalid = brow < N;

    float acc[8][8] = {};

    for (int k0 = 0; k0 < K; k0 += BK) {
        #pragma unroll
        for (int i = 0; i < 8; i++) {
            const int gc = k0 + lk0 + i;
            As[lk0 + i][lrow] = (gc < K) ? Arow[gc] : 0.f;
            Bs[lk0 + i][lrow] = (bvalid && gc < K) ? Brow[gc] : 0.f;
        }
        __syncthreads();

        #pragma unroll
        for (int k = 0; k < BK; k++) {
            const float4 a0 = *(const float4*)&As[k][r0];
            const float4 a1 = *(const float4*)&As[k][r0 + 16];
            const float4 b0 = *(const float4*)&Bs[k][c0];
            const float4 b1 = *(const float4*)&Bs[k][c0 + 32];
            const float av[8] = {a0.x, a0.y, a0.z, a0.w, a1.x, a1.y, a1.z, a1.w};
            const float bv[8] = {b0.x, b0.y, b0.z, b0.w, b1.x, b1.y, b1.z, b1.w};
            #pragma unroll
            for (int i = 0; i < 8; i++)
                #pragma unroll
                for (int j = 0; j < 8; j++)
                    acc[i][j] += av[i] * bv[j];
        }
        __syncthreads();
    }

    #pragma unroll
    for (int i = 0; i < 8; i++) {
        const int r = row0 + r0 + ((i < 4) ? i : (16 + i - 4));
        #pragma unroll
        for (int j = 0; j < 8; j++) {
            const int c = col0 + c0 + ((j < 4) ? j : (32 + j - 4));
            if (c < N) C[(size_t)r * N + c] = acc[i][j] + bias[c];
        }
    }
}

// ---------------- GRU recurrence: 8-CTA cluster, mbarrier tx-count sync ------
//
// Warp w of CTA c owns hidden unit j = c*32 + w (W_hh rows j, j+256, j+512 in
// registers, 24 fp32/thread). Per step: try_wait on this buffer's mbarrier
// (1024B = 256 warps x 4B of h delivered via st.async), LDS slice, 24 FMAs,
// 3x 5-round shfl butterfly, gate math in ALL lanes (warp-uniform), lanes 0..7
// each st.async h_new[j] to cluster CTA d=lane, completing the remote
// mbarrier's tx count. No barrier.cluster, no __syncthreads in the loop.
//
// 2-buffer safety is causal: a gen g+2 store can only be issued by a producer
// that consumed gen g+1, which required THIS CTA's gen g+1 store, which was
// issued only after this CTA passed its gen-g wait (barrier already flipped).

__device__ __forceinline__ uint32_t smem_u32(const void* p) {
    uint32_t a;
    asm("{ .reg .u64 t; cvta.to.shared.u64 t, %1; cvt.u32.u64 %0, t; }"
        : "=r"(a) : "l"(p));
    return a;
}

__device__ __forceinline__ float sigmoid_fast(float x) {
    return __fdividef(1.f, 1.f + __expf(-x));
}
__device__ __forceinline__ float tanh_fast(float x) {
    return 1.f - __fdividef(2.f, __expf(2.f * x) + 1.f);
}

__device__ __forceinline__ void mbar_wait_acq_cluster(uint32_t mb, uint32_t parity) {
    asm volatile(
        "{\n\t.reg .pred P;\n\t"
        "LW_%=:\n\t"
        "mbarrier.try_wait.parity.acquire.cluster.shared::cta.b64 P, [%0], %1, 0x989680;\n\t"
        "@P bra LD_%=;\n\t"
        "bra LW_%=;\n\t"
        "LD_%=:\n\t}"
        :: "r"(mb), "r"(parity) : "memory");
}

__global__ void __cluster_dims__(NCTA, 1, 1) __launch_bounds__(1024, 1)
gru_kernel(const float* __restrict__ xproj, const float* __restrict__ Whh,
           const float* __restrict__ bhh,   const float* __restrict__ h0,
           float* __restrict__ hs_out,      float* __restrict__ hT_out)
{
    __shared__ __align__(16) float h_buf[2][H_DIM];
    __shared__ __align__(8)  unsigned long long mbar[2];

    const int tid  = threadIdx.x;
    const int wid  = tid >> 5;
    const int lane = tid & 31;
    uint32_t rank;
    asm("mov.u32 %0, %%cluster_ctarank;" : "=r"(rank));
    const int j = (int)rank * 32 + wid;          // hidden unit owned by this warp

    // Register-resident weights: rows j (r), j+256 (z), j+512 (n), cols [8*lane, 8*lane+8)
    float w0[8], w1[8], w2[8];
    {
        const float4* p0 = (const float4*)(Whh + (size_t)j * H_DIM + lane * 8);
        const float4* p1 = (const float4*)(Whh + (size_t)(j + 256) * H_DIM + lane * 8);
        const float4* p2 = (const float4*)(Whh + (size_t)(j + 512) * H_DIM + lane * 8);
        float4 a = p0[0], b = p0[1];
        w0[0]=a.x; w0[1]=a.y; w0[2]=a.z; w0[3]=a.w; w0[4]=b.x; w0[5]=b.y; w0[6]=b.z; w0[7]=b.w;
        a = p1[0]; b = p1[1];
        w1[0]=a.x; w1[1]=a.y; w1[2]=a.z; w1[3]=a.w; w1[4]=b.x; w1[5]=b.y; w1[6]=b.z; w1[7]=b.w;
        a = p2[0]; b = p2[1];
        w2[0]=a.x; w2[1]=a.y; w2[2]=a.z; w2[3]=a.w; w2[4]=b.x; w2[5]=b.y; w2[6]=b.z; w2[7]=b.w;
    }
    const float bhr = bhh[j], bhz = bhh[j + 256], bhn = bhh[j + 512];

    const uint32_t hbase_loc = smem_u32(&h_buf[0][0]);
    const uint32_t mbar_loc  = smem_u32(&mbar[0]);

    // init: mbarriers (count=1) + h_0 local copy
    if (tid == 0) {
        asm volatile("mbarrier.init.shared.b64 [%0], 1;" :: "r"(mbar_loc)     : "memory");
        asm volatile("mbarrier.init.shared.b64 [%0], 1;" :: "r"(mbar_loc + 8) : "memory");
    }
    if (tid < H_DIM) h_buf[0][tid] = h0 ? h0[tid] : 0.f;
    __syncthreads();
    // pre-post expectations for the first fill of each buffer (h_1 -> buf1, h_2 -> buf0)
    if (tid == 0) {
        asm volatile("mbarrier.arrive.expect_tx.shared::cta.b64 _, [%0], 1024;" :: "r"(mbar_loc)     : "memory");
        asm volatile("mbarrier.arrive.expect_tx.shared::cta.b64 _, [%0], 1024;" :: "r"(mbar_loc + 8) : "memory");
    }
    float hold = h_buf[0][j];        // register-carried h_old[j] from here on
    // one-time cluster sync: peers' mbarriers valid before any st.async flies
    asm volatile("barrier.cluster.arrive.aligned;" ::: "memory");
    asm volatile("barrier.cluster.wait.aligned;"   ::: "memory");

    // per-destination remote addresses (lanes 0..7), computed once
    uint32_t ra_h = 0, ra_m = 0;
    if (lane < NCTA) {
        asm("mapa.shared::cluster.u32 %0, %1, %2;" : "=r"(ra_h) : "r"(hbase_loc), "r"(lane));
        asm("mapa.shared::cluster.u32 %0, %1, %2;" : "=r"(ra_m) : "r"(mbar_loc),  "r"(lane));
    }

    int ph0 = 0, ph1 = 0;

    for (int t = 0; t < T_LEN; t++) {
        const int p = t & 1;

        // prefetch xproj row (uniform per warp; independent of h) before the wait
        const float* row = xproj + (size_t)t * G3;
        const float xr = row[j], xz = row[j + 256], xn = row[j + 512];

        if (t > 0) {
            const uint32_t mb = mbar_loc + (uint32_t)p * 8;
            mbar_wait_acq_cluster(mb, (uint32_t)(p ? ph1 : ph0));
            if (p) ph1 ^= 1; else ph0 ^= 1;
            // repost this buffer's expectation for its next fill (gen t+2)
            if (tid == 9)
                asm volatile("mbarrier.arrive.expect_tx.shared::cta.b64 _, [%0], 1024;"
                             :: "r"(mb) : "memory");
        }

        // matvec partials over this lane's 8 h values
        const float4* hb = (const float4*)&h_buf[p][lane * 8];
        const float4 hv0 = hb[0], hv1 = hb[1];
        const float hv[8] = {hv0.x, hv0.y, hv0.z, hv0.w, hv1.x, hv1.y, hv1.z, hv1.w};
        float a0 = 0.f, a1 = 0.f, a2 = 0.f;
        #pragma unroll
        for (int k = 0; k < 8; k++) {
            a0 += w0[k] * hv[k];
            a1 += w1[k] * hv[k];
            a2 += w2[k] * hv[k];
        }
        // 3 independent 5-round butterflies (chains overlap; ~150 cyc total)
        #pragma unroll
        for (int off = 16; off > 0; off >>= 1) {
            a0 += __shfl_xor_sync(0xffffffffu, a0, off);
            a1 += __shfl_xor_sync(0xffffffffu, a1, off);
            a2 += __shfl_xor_sync(0xffffffffu, a2, off);
        }

        // gate combine in all lanes (warp-uniform inputs)
        const float r    = sigmoid_fast(xr + a0 + bhr);
        const float z    = sigmoid_fast(xz + a1 + bhz);
        const float n    = tanh_fast(xn + r * (a2 + bhn));
        const float hnew = n + z * (hold - n);     // (1-z)*n + z*h
        hold = hnew;

        if (t < T_LEN - 1) {
            // lanes 0..7: deliver h_new[j] to buffer (1-p) of cluster CTA d=lane,
            // completing 4B of tx on that CTA's mbar[1-p]
            if (lane < NCTA) {
                const uint32_t daddr = ra_h + (uint32_t)(((1 - p) * H_DIM + j) << 2);
                const uint32_t dmbar = ra_m + (uint32_t)((1 - p) * 8);
                asm volatile(
                    "st.async.shared::cluster.mbarrier::complete_tx::bytes.b32 [%0], %1, [%2];"
                    :: "r"(daddr), "r"(__float_as_uint(hnew)), "r"(dmbar) : "memory");
            }
        }
        if (lane == 8) {
            if (hs_out) hs_out[(size_t)t * H_DIM + j] = hnew;
            if (t == T_LEN - 1 && hT_out) hT_out[j] = hnew;
        }
    }

    // no st.async issued for the final step -> no in-flight traffic; sync & exit
    asm volatile("barrier.cluster.arrive.aligned;" ::: "memory");
    asm volatile("barrier.cluster.wait.aligned;"   ::: "memory");
}

// ---------------- launch --------------------------------------------------------
extern "C" void kernel_launch(void* const* d_in, const int* in_sizes, int n_in,
                              void* d_out, int out_size)
{
    const float* x      = (const float*)d_in[0];   // [1, T, I]
    const float* W_ih_e = (const float*)d_in[2];   // [768, 1739]
    const float* W_hh_e = (const float*)d_in[3];   // [768, 256]
    const float* b_ih_e = (const float*)d_in[4];   // [768]
    const float* b_hh_e = (const float*)d_in[5];   // [768]
    const float* W_ih_d = (const float*)d_in[6];
    const float* W_hh_d = (const float*)d_in[7];
    const float* b_ih_d = (const float*)d_in[8];
    const float* b_hh_d = (const float*)d_in[9];
    const float* W_out  = (const float*)d_in[10];  // [1739, 256]
    const float* b_out  = (const float*)d_in[11];  // [1739]
    float* out = (float*)d_out;                    // [2048, 1, 1739]

    float *xpe, *xpd, *hs, *henc;
    cudaGetSymbolAddress((void**)&xpe,  g_xproj_enc);
    cudaGetSymbolAddress((void**)&xpd,  g_xproj_dec);
    cudaGetSymbolAddress((void**)&hs,   g_hs);
    cudaGetSymbolAddress((void**)&henc, g_henc);

    const dim3 blk(256);
    // x-projections (independent)
    gemm_bias_kernel<<<dim3(G3 / BN, T_LEN / BM), blk>>>(x, W_ih_e, b_ih_e, xpe,
                                                         T_LEN, G3, I_DIM);
    gemm_bias_kernel<<<dim3(G3 / BN, T_LEN / BM), blk>>>(x, W_ih_d, b_ih_d, xpd,
                                                         T_LEN, G3, I_DIM);
    // encoder recurrence -> h_enc
    gru_kernel<<<NCTA, 1024>>>(xpe, W_hh_e, b_hh_e, nullptr, nullptr, henc);
    // decoder recurrence (h0 = h_enc) -> hs
    gru_kernel<<<NCTA, 1024>>>(xpd, W_hh_d, b_hh_d, henc, hs, nullptr);
    // output projection
    gemm_bias_kernel<<<dim3((I_DIM + BN - 1) / BN, T_LEN / BM), blk>>>(
        hs, W_out, b_out, out, T_LEN, I_DIM, H_DIM);
}